// round 3
// baseline (speedup 1.0000x reference)
#include <cuda_runtime.h>

// ConvEnhanced: 2x2 valid conv + ReLU -> channel 0.
// Quantum circuit collapses analytically: RZ layers are diagonal phases,
// CNOT layers are permutations; Z0 after two CNOT layers = Z0*Z1*Z3 on the
// RX product state => qval = cos(p00)*cos(p01)*cos(p11). qparams unused.
// Channel 1 = qval replicated over each 2x2 patch.
//
// x: [64,1,257,257] f32; out: [64,2,256,256] f32.
//
// Block = 4 patch-rows x 128 patch-cols of one image.
//   stage 9 contiguous input rows (2313 f32) into smem with unit-stride
//   coalesced loads (no L1 duplication), rows padded to 260 for aligned
//   conflict-free LDS.128 in the compute phase.
// Thread = 2 horizontal patches -> all-STG.128 output.

#define IN_HW   257
#define OUT_HW  256
#define SROW    260              // smem row stride (multiple of 4)
#define PR      4                // patch rows per block
#define SROWS   (2*PR + 1)       // 9 input rows staged
#define NLOAD   (SROWS * IN_HW)  // 2313 floats

__global__ __launch_bounds__(256)
void conv_enhanced_kernel(const float* __restrict__ x,
                          const float* __restrict__ w,
                          const float* __restrict__ bias,
                          float* __restrict__ out)
{
    __shared__ float s[SROWS * SROW];

    const int b    = blockIdx.x >> 5;        // image
    const int tile = blockIdx.x & 31;        // 4-patch-row strip
    const int tid  = threadIdx.x;

    // ---- stage: 9 contiguous rows, unit-stride coalesced ----
    const float* src = x + (size_t)b * (IN_HW * IN_HW) + (size_t)tile * (2 * PR) * IN_HW;
#pragma unroll
    for (int i = tid; i < NLOAD; i += 256) {
        const int row = i / IN_HW;
        const int col = i - row * IN_HW;
        s[row * SROW + col] = __ldg(src + i);
    }
    __syncthreads();

    // ---- compute: thread -> (pr, patch-pair pp) ----
    const int pr = tid >> 6;                 // 0..3
    const int pp = tid & 63;                 // 0..63
    const int c  = pp * 4;                   // smem col of first tap (16B aligned)

    const float w00 = __ldg(w + 0);
    const float w01 = __ldg(w + 1);
    const float w10 = __ldg(w + 2);
    const float w11 = __ldg(w + 3);
    const float bb  = __ldg(bias);

    const int r0 = 2 * pr;
    const float4 v0 = *reinterpret_cast<const float4*>(&s[(r0 + 0) * SROW + c]);
    const float4 v1 = *reinterpret_cast<const float4*>(&s[(r0 + 1) * SROW + c]);
    const float4 v2 = *reinterpret_cast<const float4*>(&s[(r0 + 2) * SROW + c]);
    const float e0 = s[(r0 + 0) * SROW + c + 4];
    const float e1 = s[(r0 + 1) * SROW + c + 4];
    const float e2 = s[(r0 + 2) * SROW + c + 4];

    const float x0[5] = { v0.x, v0.y, v0.z, v0.w, e0 };
    const float x1[5] = { v1.x, v1.y, v1.z, v1.w, e1 };
    const float x2[5] = { v2.x, v2.y, v2.z, v2.w, e2 };

    float p0[4], p1[4];
#pragma unroll
    for (int j = 0; j < 4; ++j) {
        p0[j] = fmaxf(fmaf(w00, x0[j], fmaf(w01, x0[j+1],
                        fmaf(w10, x1[j], fmaf(w11, x1[j+1], bb)))), 0.f);
        p1[j] = fmaxf(fmaf(w00, x1[j], fmaf(w01, x1[j+1],
                        fmaf(w10, x2[j], fmaf(w11, x2[j+1], bb)))), 0.f);
    }

    const float qA = __cosf(p0[0]) * __cosf(p0[1]) * __cosf(p1[1]);
    const float qB = __cosf(p0[2]) * __cosf(p0[3]) * __cosf(p1[3]);

    float* ob = out + (size_t)b * (2 * OUT_HW * OUT_HW);
    const int orow = (tile * PR + pr) * 2;
    const int o0   = orow * OUT_HW + c;      // 16B aligned

    *reinterpret_cast<float4*>(ob + o0)          = make_float4(p0[0], p0[1], p0[2], p0[3]);
    *reinterpret_cast<float4*>(ob + o0 + OUT_HW) = make_float4(p1[0], p1[1], p1[2], p1[3]);

    float* ob1 = ob + OUT_HW * OUT_HW;
    const float4 qv = make_float4(qA, qA, qB, qB);
    *reinterpret_cast<float4*>(ob1 + o0)          = qv;
    *reinterpret_cast<float4*>(ob1 + o0 + OUT_HW) = qv;
}

extern "C" void kernel_launch(void* const* d_in, const int* in_sizes, int n_in,
                              void* d_out, int out_size)
{
    const float* x      = (const float*)d_in[0];
    const float* conv_w = (const float*)d_in[1];
    const float* conv_b = (const float*)d_in[2];
    // d_in[3] = qparams: provably unused
    float* out = (float*)d_out;

    conv_enhanced_kernel<<<64 * 32, 256>>>(x, conv_w, conv_b, out);
}